// round 13
// baseline (speedup 1.0000x reference)
#include <cuda_runtime.h>

// PositionEmbeddingEncoder — wavefront-minimized mapping + L2 class hints (R7).
// lane t: point = pair*2 + (t>>4), depth = ((t>>1)&7)+1, half = t&1.
// Gather: lanes 2k,2k+1 read the two 16B halves of the SAME 32B table row
//   -> 16 distinct 128B lines per LDG.128 (vs 32 for point-per-thread).
// Store: (lane&15)*16B within the 256B point row -> 4 lines per STG.128.
// U=4 keeps regs <= 32 so 8 blocks/SM (64 warps): occupancy is the
// latency-hiding mechanism (R4: U=8 -> 56 regs -> 2x slower).
// L2 policy: w6/w7 (72MB, only tables with reuse) load with an evict_last
// cache-policy register (ptxas rejects the direct qualifier on .v4.f32);
// w8 (512MB single-use) loads evict-first; output stores evict-first.

#define HALF_SIZE  128.0f
#define U          4              // point-pairs per warp (unrolled)

__device__ __forceinline__ unsigned long long mk_evict_last_policy() {
    unsigned long long pol;
    asm("createpolicy.fractional.L2::evict_last.b64 %0, 1.0;" : "=l"(pol));
    return pol;
}

__device__ __forceinline__ float4 ldg_policy(const float4* p, unsigned long long pol) {
    float4 v;
    asm volatile("ld.global.nc.L2::cache_hint.v4.f32 {%0,%1,%2,%3}, [%4], %5;"
                 : "=f"(v.x), "=f"(v.y), "=f"(v.z), "=f"(v.w)
                 : "l"(p), "l"(pol));
    return v;
}

__global__ __launch_bounds__(256, 8)
void pee_kernel(const float* __restrict__ x,
                const float* __restrict__ w1,
                const float* __restrict__ w2,
                const float* __restrict__ w3,
                const float* __restrict__ w4,
                const float* __restrict__ w5,
                const float* __restrict__ w6,
                const float* __restrict__ w7,
                const float* __restrict__ w8,
                float* __restrict__ out,
                int n)
{
    const int lane   = threadIdx.x & 31;
    const int warpid = (blockIdx.x * (blockDim.x >> 5)) + (threadIdx.x >> 5);

    const int dm = (lane >> 1) & 7;       // 0..7  -> depth = dm+1
    const int h  = lane & 1;              // row half
    const int ps = lane >> 4;             // 0/1: which point of the pair

    const float* wp;
    switch (dm) {
        case 0: wp = w1; break;
        case 1: wp = w2; break;
        case 2: wp = w3; break;
        case 3: wp = w4; break;
        case 4: wp = w5; break;
        case 5: wp = w6; break;
        case 6: wp = w7; break;
        default: wp = w8; break;
    }

    const int   depth = dm + 1;
    const int   g     = 1 << depth;
    // (x+128) * (g/256): both scalings are exact powers of two, so this is
    // bit-identical to ((x+128)/256)*g as computed by the reference.
    const float kf    = (float)g * (1.0f / 256.0f);
    const bool  deep  = (dm == 7);               // w8: single-use, evict-first
    const bool  mid   = (dm == 5) || (dm == 6);  // w6/w7: L2-reusable, pin

    const unsigned long long pol = mk_evict_last_policy();

    const int pt0 = warpid * (U * 2) + ps;

    float4 v[U];
    int    p[U];

#pragma unroll
    for (int u = 0; u < U; u++) {
        int pt = pt0 + u * 2;
        p[u] = pt;
        if (pt < n) {
            float fx = (x[3 * pt + 0] + HALF_SIZE) * kf;
            float fy = (x[3 * pt + 1] + HALF_SIZE) * kf;
            float fz = (x[3 * pt + 2] + HALF_SIZE) * kf;

            int gx = min(max(__float2int_rd(fx), 0), g - 1);
            int gy = min(max(__float2int_rd(fy), 0), g - 1);
            int gz = min(max(__float2int_rd(fz), 0), g - 1);

            unsigned int flat = (unsigned int)gx
                              + ((unsigned int)gy << depth)
                              + ((unsigned int)gz << (2 * depth));

            const float4* addr = (const float4*)(wp + (size_t)flat * 8 + h * 4);
            if (deep)
                v[u] = __ldcs(addr);            // evict-first: single-use w8
            else if (mid)
                v[u] = ldg_policy(addr, pol);   // pin w6/w7 in L2
            else
                v[u] = __ldg(addr);             // tiny tables, L1-resident
        }
    }

#pragma unroll
    for (int u = 0; u < U; u++) {
        if (p[u] < n) {
            __stcs((float4*)(out + (size_t)p[u] * 64) + (lane & 15), v[u]);
        }
    }
}

extern "C" void kernel_launch(void* const* d_in, const int* in_sizes, int n_in,
                              void* d_out, int out_size)
{
    const float* x  = (const float*)d_in[0];
    const float* w1 = (const float*)d_in[1];
    const float* w2 = (const float*)d_in[2];
    const float* w3 = (const float*)d_in[3];
    const float* w4 = (const float*)d_in[4];
    const float* w5 = (const float*)d_in[5];
    const float* w6 = (const float*)d_in[6];
    const float* w7 = (const float*)d_in[7];
    const float* w8 = (const float*)d_in[8];
    float* out = (float*)d_out;

    int n = in_sizes[0] / 3;

    // one warp covers U pairs = 2*U points; 8 warps per block
    int pts_per_block = 8 * U * 2;                   // 64
    int blocks = (n + pts_per_block - 1) / pts_per_block;
    pee_kernel<<<blocks, 256>>>(x, w1, w2, w3, w4, w5, w6, w7, w8, out, n);
}

// round 14
// speedup vs baseline: 1.0411x; 1.0411x over previous
#include <cuda_runtime.h>

// PositionEmbeddingEncoder — wavefront-minimized mapping + smem x-staging (R10).
// lane t: point = pair*2 + (t>>4), depth = ((t>>1)&7)+1, half = t&1.
// Gather: lanes 2k,2k+1 read the two 16B halves of the SAME 32B table row
//   -> 16 distinct 128B lines per LDG.128 (vs 32 for point-per-thread).
// Store: (lane&15)*16B within the 256B point row -> 4 lines per STG.128.
// x: block-cooperatively staged into smem (64 pts * 3 floats, coalesced,
//   6 wavefronts/block) replacing ~192 scattered global wf/block, and
//   removing the per-gather x->flat DRAM dependency chain.
// U=4 + (256,8) launch bounds keep regs <= 32 -> 64 warps/SM (R4 lesson:
// occupancy is the latency-hiding mechanism here).

#define HALF_SIZE  128.0f
#define U          4              // point-pairs per warp (unrolled)
#define WARPS_PB   8
#define PTS_PB     (WARPS_PB * U * 2)   // 64 points per block

__global__ __launch_bounds__(256, 8)
void pee_kernel(const float* __restrict__ x,
                const float* __restrict__ w1,
                const float* __restrict__ w2,
                const float* __restrict__ w3,
                const float* __restrict__ w4,
                const float* __restrict__ w5,
                const float* __restrict__ w6,
                const float* __restrict__ w7,
                const float* __restrict__ w8,
                float* __restrict__ out,
                int n)
{
    __shared__ float xs[PTS_PB * 3];     // 768 B

    const int tid  = threadIdx.x;
    const int lane = tid & 31;
    const int warp = tid >> 5;

    // ---- cooperative, coalesced x staging ----
    {
        int base = blockIdx.x * (PTS_PB * 3);
        if (tid < PTS_PB * 3) {
            int gidx = base + tid;
            xs[tid] = (gidx < n * 3) ? x[gidx] : 0.0f;
        }
    }
    __syncthreads();

    const int dm = (lane >> 1) & 7;       // 0..7  -> depth = dm+1
    const int h  = lane & 1;              // row half
    const int ps = lane >> 4;             // 0/1: which point of the pair

    const float* wp;
    switch (dm) {
        case 0: wp = w1; break;
        case 1: wp = w2; break;
        case 2: wp = w3; break;
        case 3: wp = w4; break;
        case 4: wp = w5; break;
        case 5: wp = w6; break;
        case 6: wp = w7; break;
        default: wp = w8; break;
    }

    const int   depth = dm + 1;
    const int   g     = 1 << depth;
    // (x+128) * (g/256): both scalings are exact powers of two, so this is
    // bit-identical to ((x+128)/256)*g as computed by the reference.
    const float kf    = (float)g * (1.0f / 256.0f);

    const int lp0     = warp * (U * 2) + ps;            // local point base
    const int pt_base = blockIdx.x * PTS_PB + lp0;      // global point base

    float4 v[U];

#pragma unroll
    for (int u = 0; u < U; u++) {
        int lp = lp0 + u * 2;
        int pt = pt_base + u * 2;
        if (pt < n) {
            float fx = (xs[lp * 3 + 0] + HALF_SIZE) * kf;
            float fy = (xs[lp * 3 + 1] + HALF_SIZE) * kf;
            float fz = (xs[lp * 3 + 2] + HALF_SIZE) * kf;

            int gx = min(max(__float2int_rd(fx), 0), g - 1);
            int gy = min(max(__float2int_rd(fy), 0), g - 1);
            int gz = min(max(__float2int_rd(fz), 0), g - 1);

            unsigned int flat = (unsigned int)gx
                              + ((unsigned int)gy << depth)
                              + ((unsigned int)gz << (2 * depth));

            v[u] = __ldg((const float4*)(wp + (size_t)flat * 8 + h * 4));
        }
    }

#pragma unroll
    for (int u = 0; u < U; u++) {
        int pt = pt_base + u * 2;
        if (pt < n) {
            __stcs((float4*)(out + (size_t)pt * 64) + (lane & 15), v[u]);
        }
    }
}

extern "C" void kernel_launch(void* const* d_in, const int* in_sizes, int n_in,
                              void* d_out, int out_size)
{
    const float* x  = (const float*)d_in[0];
    const float* w1 = (const float*)d_in[1];
    const float* w2 = (const float*)d_in[2];
    const float* w3 = (const float*)d_in[3];
    const float* w4 = (const float*)d_in[4];
    const float* w5 = (const float*)d_in[5];
    const float* w6 = (const float*)d_in[6];
    const float* w7 = (const float*)d_in[7];
    const float* w8 = (const float*)d_in[8];
    float* out = (float*)d_out;

    int n = in_sizes[0] / 3;

    int blocks = (n + PTS_PB - 1) / PTS_PB;
    pee_kernel<<<blocks, 256>>>(x, w1, w2, w3, w4, w5, w6, w7, w8, out, n);
}